// round 5
// baseline (speedup 1.0000x reference)
#include <cuda_runtime.h>
#include <math.h>
#include <float.h>

#define NB   8
#define ND   1024
#define NHH  16
#define HDm  64
#define HW   4096
#define NS   4097   // 1 CLS + 4096 tokens

// ---------------- scratch (device globals; no allocations) ----------------
__device__ float g_pe[ND * HW];          // [d][p] positional encoding (16 MB)
__device__ float g_q0[NB * ND];          // q of CLS token
__device__ float g_kcls[NB * ND];        // k of CLS token (bias included)
__device__ float g_vcls[NB * ND];        // v of CLS token (bias included)
__device__ float g_u[NB * ND * NHH];     // [b][d][h] : u = q0^T Wk (folded)
__device__ float g_t[NB * ND];           // t_b = Wo v_cls + bo
__device__ float g_ck[NB * NHH];         // q0 . bk per head
__device__ float g_scores[NB * NHH * NS];
__device__ float g_probs[NB * NS * NHH]; // [b][s][h] (transposed for pass B)
__device__ float g_m[NB * NHH * ND];     // [b][h][d] : sum_s p_s * xc_s
__device__ float g_clsout[NB * ND];      // attention output of CLS token

// ---------------- P0: positional encoding table ----------------
__global__ void kP0() {
    int d  = blockIdx.x;
    int e2 = d & ~1;
    // rate computed in double, rounded to fp32 (matches jnp fp32 pow to ~1 ulp)
    float rate = (float)exp(-(double)e2 * (9.210340371976184 / 1024.0));
    bool iscos = (d & 1);
    int base = d * HW;
    for (int p = threadIdx.x; p < HW; p += blockDim.x) {
        float ang = (float)p * rate;
        g_pe[base + p] = iscos ? cosf(ang) : sinf(ang);
    }
}

// ---------------- P1: q0 / k_cls / v_cls  (warp per Wqkv row, all batches) --
__global__ void __launch_bounds__(256) kP1(const float* __restrict__ Wqkv,
                                           const float* __restrict__ bqkv,
                                           const float* __restrict__ ctx) {
    int gw   = blockIdx.x * 8 + (threadIdx.x >> 5);  // row of Wqkv, 0..3071
    int lane = threadIdx.x & 31;
    if (gw >= 3 * ND) return;
    const float* row = Wqkv + (size_t)gw * ND;
    float acc[NB];
#pragma unroll
    for (int b = 0; b < NB; b++) acc[b] = 0.f;
    for (int e = lane; e < ND; e += 32) {
        float wv = row[e];
#pragma unroll
        for (int b = 0; b < NB; b++) acc[b] += wv * ctx[b * ND + e];
    }
#pragma unroll
    for (int b = 0; b < NB; b++) {
#pragma unroll
        for (int off = 16; off; off >>= 1)
            acc[b] += __shfl_xor_sync(0xffffffffu, acc[b], off);
    }
    if (lane == 0) {
        float bias = bqkv[gw];
        float* dst;
        if (gw < ND)            dst = g_q0   + gw;
        else if (gw < 2 * ND)   dst = g_kcls + (gw - ND);
        else                    dst = g_vcls + (gw - 2 * ND);
#pragma unroll
        for (int b = 0; b < NB; b++) dst[b * ND] = acc[b] + bias;
    }
}

// ---------------- P2: u, t, ck, CLS score ----------------
__global__ void __launch_bounds__(256) kP2(const float* __restrict__ Wqkv,
                                           const float* __restrict__ bqkv,
                                           const float* __restrict__ Wo,
                                           const float* __restrict__ bo) {
    int bx = blockIdx.x;
    if (bx < 16) {
        // u[b][d][h] = sum_j q0[b][h*64+j] * Wk[h*64+j][d]    (block = head h)
        int h = bx;
        __shared__ float s_q[NB * HDm];
        for (int i = threadIdx.x; i < NB * HDm; i += blockDim.x) {
            int b = i >> 6, j = i & 63;
            s_q[i] = g_q0[b * ND + h * HDm + j];
        }
        __syncthreads();
        for (int d = threadIdx.x; d < ND; d += blockDim.x) {
            float acc[NB];
#pragma unroll
            for (int b = 0; b < NB; b++) acc[b] = 0.f;
            for (int j = 0; j < HDm; j++) {
                float wv = Wqkv[(size_t)(ND + h * HDm + j) * ND + d];
#pragma unroll
                for (int b = 0; b < NB; b++) acc[b] += s_q[b * HDm + j] * wv;
            }
#pragma unroll
            for (int b = 0; b < NB; b++)
                g_u[(size_t)(b * ND + d) * NHH + h] = acc[b];
        }
    } else if (bx < 144) {
        // t[b][d] = bo[d] + sum_e Wo[d][e] * vcls[b][e]   (warp per d)
        int d    = (bx - 16) * 8 + (threadIdx.x >> 5);
        int lane = threadIdx.x & 31;
        const float* row = Wo + (size_t)d * ND;
        float acc[NB];
#pragma unroll
        for (int b = 0; b < NB; b++) acc[b] = 0.f;
        for (int e = lane; e < ND; e += 32) {
            float wv = row[e];
#pragma unroll
            for (int b = 0; b < NB; b++) acc[b] += wv * g_vcls[b * ND + e];
        }
#pragma unroll
        for (int b = 0; b < NB; b++) {
#pragma unroll
            for (int off = 16; off; off >>= 1)
                acc[b] += __shfl_xor_sync(0xffffffffu, acc[b], off);
        }
        if (lane == 0) {
            float bias = bo[d];
#pragma unroll
            for (int b = 0; b < NB; b++) g_t[b * ND + d] = acc[b] + bias;
        }
    } else {
        // ck[b][h] = q0 . bk_h ;  scores[b][h][0] = 0.125 * q0 . k_cls
        int t = threadIdx.x;
        if (t < NB * NHH) {
            int b = t >> 4, h = t & 15;
            float ck = 0.f, s0 = 0.f;
            for (int j = 0; j < HDm; j++) {
                float q = g_q0[b * ND + h * HDm + j];
                ck += q * bqkv[ND + h * HDm + j];
                s0 += q * g_kcls[b * ND + h * HDm + j];
            }
            g_ck[t] = ck;
            g_scores[(size_t)t * NS] = s0 * 0.125f;
        }
    }
}

// ---------------- Pass A: scores + LayerNorm feature-map output ----------------
// block = (b, tile of 32 tokens). 8 warps, warp w handles d = i*8+w.
__global__ void __launch_bounds__(256) kA(const float* __restrict__ x,
                                          const float* __restrict__ gamma,
                                          const float* __restrict__ beta,
                                          float* __restrict__ out) {
    int b    = blockIdx.y;
    int p0   = blockIdx.x * 32;
    int w    = threadIdx.x >> 5;
    int lane = threadIdx.x & 31;
    int p    = p0 + lane;

    __shared__ float s_acc[8][16][32];
    __shared__ float s_sum[8][32];
    __shared__ float s_sq[8][32];
    __shared__ float s_mu[32];
    __shared__ float s_rs[32];

    const float* xb = x   + (size_t)b * ND * HW;
    const float* tb = g_t + b * ND;
    const float* ub = g_u + (size_t)b * ND * NHH;

    float acc[16];
#pragma unroll
    for (int h = 0; h < 16; h++) acc[h] = 0.f;
    float lsum = 0.f, lsq = 0.f;

#pragma unroll 4
    for (int i = 0; i < 128; i++) {
        int d = i * 8 + w;
        int off = d * HW + p;
        float xc = __ldg(xb + off) + g_pe[off];
        float r  = xc + __ldg(tb + d);
        lsum += r;
        lsq  += r * r;
        const float4* u4 = (const float4*)(ub + (size_t)d * NHH);
        float4 u0 = u4[0], u1 = u4[1], u2 = u4[2], u3 = u4[3];
        acc[0]  += u0.x * xc;  acc[1]  += u0.y * xc;
        acc[2]  += u0.z * xc;  acc[3]  += u0.w * xc;
        acc[4]  += u1.x * xc;  acc[5]  += u1.y * xc;
        acc[6]  += u1.z * xc;  acc[7]  += u1.w * xc;
        acc[8]  += u2.x * xc;  acc[9]  += u2.y * xc;
        acc[10] += u2.z * xc;  acc[11] += u2.w * xc;
        acc[12] += u3.x * xc;  acc[13] += u3.y * xc;
        acc[14] += u3.z * xc;  acc[15] += u3.w * xc;
    }

    s_sum[w][lane] = lsum;
    s_sq[w][lane]  = lsq;
#pragma unroll
    for (int h = 0; h < 16; h++) s_acc[w][h][lane] = acc[h];
    __syncthreads();

    if (threadIdx.x < 32) {
        int tok = threadIdx.x;
        float m = 0.f, q = 0.f;
#pragma unroll
        for (int ww = 0; ww < 8; ww++) { m += s_sum[ww][tok]; q += s_sq[ww][tok]; }
        float mu  = m * (1.f / 1024.f);
        float var = q * (1.f / 1024.f) - mu * mu;
        s_mu[tok] = mu;
        s_rs[tok] = rsqrtf(var + 1e-5f);
    }
    // scores: 512 (h,tok) pairs
    for (int pair = threadIdx.x; pair < 512; pair += 256) {
        int h = pair >> 5, tok = pair & 31;
        float sc = 0.f;
#pragma unroll
        for (int ww = 0; ww < 8; ww++) sc += s_acc[ww][h][tok];
        sc = (sc + g_ck[b * NHH + h]) * 0.125f;
        g_scores[(size_t)(b * NHH + h) * NS + (p0 + tok + 1)] = sc;
    }
    __syncthreads();

    float mu = s_mu[lane];
    float rs = s_rs[lane];
    float* ob = out + (size_t)b * ND * HW;
#pragma unroll 4
    for (int i = 0; i < 128; i++) {
        int d = i * 8 + w;
        int off = d * HW + p;
        float xc = __ldg(xb + off) + g_pe[off];
        float r  = xc + __ldg(tb + d);
        float y  = (r - mu) * rs * __ldg(gamma + d) + __ldg(beta + d);
        ob[off] = y;
    }
}

// ---------------- Softmax over s (row = (b,h), len 4097) ----------------
__global__ void __launch_bounds__(256) kSM() {
    int bh = blockIdx.x;
    const float* sc = g_scores + (size_t)bh * NS;
    __shared__ float sred[8];
    __shared__ float sbc;
    int tid = threadIdx.x, w = tid >> 5, lane = tid & 31;

    float mx = -FLT_MAX;
    for (int s = tid; s < NS; s += 256) mx = fmaxf(mx, sc[s]);
#pragma unroll
    for (int off = 16; off; off >>= 1) mx = fmaxf(mx, __shfl_xor_sync(0xffffffffu, mx, off));
    if (lane == 0) sred[w] = mx;
    __syncthreads();
    if (tid == 0) {
        float m = sred[0];
#pragma unroll
        for (int ww = 1; ww < 8; ww++) m = fmaxf(m, sred[ww]);
        sbc = m;
    }
    __syncthreads();
    mx = sbc;
    __syncthreads();

    float sum = 0.f;
    for (int s = tid; s < NS; s += 256) sum += expf(sc[s] - mx);
#pragma unroll
    for (int off = 16; off; off >>= 1) sum += __shfl_xor_sync(0xffffffffu, sum, off);
    if (lane == 0) sred[w] = sum;
    __syncthreads();
    if (tid == 0) {
        float m = 0.f;
#pragma unroll
        for (int ww = 0; ww < 8; ww++) m += sred[ww];
        sbc = m;
    }
    __syncthreads();
    float inv = 1.f / sbc;

    int b = bh >> 4, h = bh & 15;
    for (int s = tid; s < NS; s += 256)
        g_probs[((size_t)b * NS + s) * NHH + h] = expf(sc[s] - mx) * inv;
}

// ---------------- Pass B: m[b][h][d] = sum_s probs * xc ----------------
// block = (b, 32 d's); 8 warps x 4 d each; probs chunk staged h-major in smem.
#define SCHUNK 512
__global__ void __launch_bounds__(256) kB(const float* __restrict__ x,
                                          const float* __restrict__ ctx) {
    int b     = blockIdx.x >> 5;
    int d0    = (blockIdx.x & 31) * 32;
    int tid   = threadIdx.x;
    int w     = tid >> 5, lane = tid & 31;
    int dbase = d0 + w * 4;

    __shared__ float2 s_pr[8][SCHUNK + 2];   // [h/2][s_local], padded

    float acc[16][4];
#pragma unroll
    for (int h = 0; h < 16; h++)
#pragma unroll
        for (int j = 0; j < 4; j++) acc[h][j] = 0.f;

    const float* xb = x + (size_t)b * ND * HW;

    for (int c = 0; c < HW / SCHUNK; c++) {
        // stage probs rows s = c*512+1 .. +512  (transpose to h-major)
        const float4* src = (const float4*)(g_probs + ((size_t)b * NS + c * SCHUNK + 1) * NHH);
#pragma unroll
        for (int k = 0; k < 8; k++) {
            int idx = k * 256 + tid;          // 0..2047
            int sl  = idx >> 2, q = idx & 3;
            float4 v = src[idx];
            s_pr[q * 2][sl]     = make_float2(v.x, v.y);
            s_pr[q * 2 + 1][sl] = make_float2(v.z, v.w);
        }
        __syncthreads();

#pragma unroll 2
        for (int i = 0; i < SCHUNK / 32; i++) {
            int sl = i * 32 + lane;
            int p  = c * SCHUNK + sl;
            int o0 = (dbase + 0) * HW + p;
            int o1 = (dbase + 1) * HW + p;
            int o2 = (dbase + 2) * HW + p;
            int o3 = (dbase + 3) * HW + p;
            float xc0 = __ldg(xb + o0) + g_pe[o0];
            float xc1 = __ldg(xb + o1) + g_pe[o1];
            float xc2 = __ldg(xb + o2) + g_pe[o2];
            float xc3 = __ldg(xb + o3) + g_pe[o3];
#pragma unroll
            for (int hp = 0; hp < 8; hp++) {
                float2 pr = s_pr[hp][sl];
                acc[2 * hp][0]     += pr.x * xc0;
                acc[2 * hp][1]     += pr.x * xc1;
                acc[2 * hp][2]     += pr.x * xc2;
                acc[2 * hp][3]     += pr.x * xc3;
                acc[2 * hp + 1][0] += pr.y * xc0;
                acc[2 * hp + 1][1] += pr.y * xc1;
                acc[2 * hp + 1][2] += pr.y * xc2;
                acc[2 * hp + 1][3] += pr.y * xc3;
            }
        }
        __syncthreads();
    }

    // reduce across lanes (each lane held a disjoint s-subset)
#pragma unroll
    for (int h = 0; h < 16; h++)
#pragma unroll
        for (int j = 0; j < 4; j++)
#pragma unroll
            for (int off = 16; off; off >>= 1)
                acc[h][j] += __shfl_xor_sync(0xffffffffu, acc[h][j], off);

    if (lane == 0) {
#pragma unroll
        for (int h = 0; h < 16; h++) {
            float p0h = g_probs[(size_t)b * NS * NHH + h];  // s=0 (CLS)
#pragma unroll
            for (int j = 0; j < 4; j++) {
                float mval = acc[h][j] + p0h * ctx[b * ND + dbase + j];
                g_m[(size_t)(b * NHH + h) * ND + dbase + j] = mval;
            }
        }
    }
}

// ---------------- E1: cls_out = Wv . m + bv  (warp per output dim) ----------
__global__ void __launch_bounds__(256) kE1(const float* __restrict__ Wqkv,
                                           const float* __restrict__ bqkv) {
    int dq   = blockIdx.x * 8 + (threadIdx.x >> 5);  // 0..1023
    int lane = threadIdx.x & 31;
    int h    = dq >> 6;
    const float* row = Wqkv + (size_t)(2 * ND + dq) * ND;
    float acc[NB];
#pragma unroll
    for (int b = 0; b < NB; b++) acc[b] = 0.f;
    for (int e = lane; e < ND; e += 32) {
        float wv = row[e];
#pragma unroll
        for (int b = 0; b < NB; b++)
            acc[b] += wv * g_m[(size_t)(b * NHH + h) * ND + e];
    }
#pragma unroll
    for (int b = 0; b < NB; b++) {
#pragma unroll
        for (int off = 16; off; off >>= 1)
            acc[b] += __shfl_xor_sync(0xffffffffu, acc[b], off);
    }
    if (lane == 0) {
        float bias = bqkv[2 * ND + dq];
#pragma unroll
        for (int b = 0; b < NB; b++) g_clsout[b * ND + dq] = acc[b] + bias;
    }
}

// ---------------- E2: CLS row O-proj + residual + LN -> context out ---------
__global__ void __launch_bounds__(256) kE2(const float* __restrict__ Wo,
                                           const float* __restrict__ bo,
                                           const float* __restrict__ ctx,
                                           const float* __restrict__ gamma,
                                           const float* __restrict__ beta,
                                           float* __restrict__ out_ctx) {
    int b   = blockIdx.x;
    int tid = threadIdx.x, w = tid >> 5, lane = tid & 31;
    __shared__ float sr[ND];
    __shared__ float red1[8], red2[8];
    __shared__ float s_mu, s_rs;

    const float* cls = g_clsout + b * ND;
    for (int k = 0; k < 128; k++) {
        int d = k * 8 + w;
        const float* row = Wo + (size_t)d * ND;
        float a = 0.f;
        for (int e = lane; e < ND; e += 32) a += row[e] * cls[e];
#pragma unroll
        for (int off = 16; off; off >>= 1) a += __shfl_xor_sync(0xffffffffu, a, off);
        if (lane == 0) sr[d] = a + bo[d] + ctx[b * ND + d];
    }
    __syncthreads();

    float ls = 0.f, lq = 0.f;
    for (int d = tid; d < ND; d += 256) { float v = sr[d]; ls += v; lq += v * v; }
#pragma unroll
    for (int off = 16; off; off >>= 1) {
        ls += __shfl_xor_sync(0xffffffffu, ls, off);
        lq += __shfl_xor_sync(0xffffffffu, lq, off);
    }
    if (lane == 0) { red1[w] = ls; red2[w] = lq; }
    __syncthreads();
    if (tid == 0) {
        float m = 0.f, q = 0.f;
#pragma unroll
        for (int ww = 0; ww < 8; ww++) { m += red1[ww]; q += red2[ww]; }
        float mu  = m * (1.f / 1024.f);
        float var = q * (1.f / 1024.f) - mu * mu;
        s_mu = mu;
        s_rs = rsqrtf(var + 1e-5f);
    }
    __syncthreads();
    float mu = s_mu, rs = s_rs;
    for (int d = tid; d < ND; d += 256)
        out_ctx[b * ND + d] = (sr[d] - mu) * rs * gamma[d] + beta[d];
}

// ---------------- launch ----------------
extern "C" void kernel_launch(void* const* d_in, const int* in_sizes, int n_in,
                              void* d_out, int out_size) {
    const float* x     = (const float*)d_in[0];
    const float* ctx   = (const float*)d_in[1];
    const float* Wqkv  = (const float*)d_in[2];
    const float* bqkv  = (const float*)d_in[3];
    const float* Wo    = (const float*)d_in[4];
    const float* bo    = (const float*)d_in[5];
    const float* gamma = (const float*)d_in[6];
    const float* beta  = (const float*)d_in[7];
    float* out     = (float*)d_out;
    float* out_ctx = out + (size_t)NB * ND * HW;   // tuple: (feature_map, context)

    kP0<<<ND, 256>>>();
    kP1<<<384, 256>>>(Wqkv, bqkv, ctx);
    kP2<<<145, 256>>>(Wqkv, bqkv, Wo, bo);
    kA<<<dim3(HW / 32, NB), 256>>>(x, gamma, beta, out);
    kSM<<<NB * NHH, 256>>>();
    kB<<<NB * 32, 256>>>(x, ctx);
    kE1<<<128, 256>>>(Wqkv, bqkv);
    kE2<<<NB, 256>>>(Wo, bo, ctx, gamma, beta, out_ctx);
}

// round 6
// speedup vs baseline: 1.3636x; 1.3636x over previous
#include <cuda_runtime.h>
#include <math.h>
#include <float.h>

#define NB   8
#define ND   1024
#define NHH  16
#define HDm  64
#define HW   4096
#define NS   4097   // 1 CLS + 4096 tokens

typedef unsigned long long u64;

// ---------------- packed f32x2 helpers ----------------
__device__ __forceinline__ u64 pack2(float lo, float hi) {
    u64 r; asm("mov.b64 %0, {%1,%2};" : "=l"(r) : "f"(lo), "f"(hi)); return r;
}
__device__ __forceinline__ void unpack2(u64 v, float& lo, float& hi) {
    asm("mov.b64 {%0,%1}, %2;" : "=f"(lo), "=f"(hi) : "l"(v));
}
__device__ __forceinline__ void fma2(u64& d, u64 a, u64 b) {
    asm("fma.rn.f32x2 %0, %1, %2, %0;" : "+l"(d) : "l"(a), "l"(b));
}
__device__ __forceinline__ u64 fma2n(u64 a, u64 b, u64 c) {
    u64 d; asm("fma.rn.f32x2 %0, %1, %2, %3;" : "=l"(d) : "l"(a), "l"(b), "l"(c)); return d;
}
__device__ __forceinline__ u64 add2(u64 a, u64 b) {
    u64 d; asm("add.rn.f32x2 %0, %1, %2;" : "=l"(d) : "l"(a), "l"(b)); return d;
}
__device__ __forceinline__ u64 mul2(u64 a, u64 b) {
    u64 d; asm("mul.rn.f32x2 %0, %1, %2;" : "=l"(d) : "l"(a), "l"(b)); return d;
}
__device__ __forceinline__ u64 ldg2(const float* p) { return __ldg((const u64*)p); }

// ---------------- scratch (device globals; no allocations) ----------------
__device__ float g_pe[ND * HW];          // [d][p] positional encoding (16 MB)
__device__ float g_q0[NB * ND];
__device__ float g_kcls[NB * ND];
__device__ float g_vcls[NB * ND];
__device__ float g_u[NB * ND * NHH];     // [b][d][h]
__device__ float g_t[NB * ND];           // t_b = Wo v_cls + bo
__device__ float g_ck[NB * NHH];
__device__ float g_scores[NB * NHH * NS];
__device__ float g_probs[NB * NS * NHH]; // [b][s][h]
__device__ float g_m[NB * NHH * ND];
__device__ float g_clsout[NB * ND];
__device__ float g_resid[NB * ND];

// ---------------- P0: positional encoding table ----------------
__global__ void kP0() {
    int d  = blockIdx.x;
    int e2 = d & ~1;
    float rate = (float)exp(-(double)e2 * (9.210340371976184 / 1024.0));
    bool iscos = (d & 1);
    int base = d * HW;
    for (int p = threadIdx.x; p < HW; p += blockDim.x) {
        float ang = (float)p * rate;
        g_pe[base + p] = iscos ? cosf(ang) : sinf(ang);
    }
}

// ---------------- P1: q0 / k_cls / v_cls ----------------
__global__ void __launch_bounds__(256) kP1(const float* __restrict__ Wqkv,
                                           const float* __restrict__ bqkv,
                                           const float* __restrict__ ctx) {
    int gw   = blockIdx.x * 8 + (threadIdx.x >> 5);
    int lane = threadIdx.x & 31;
    if (gw >= 3 * ND) return;
    const float* row = Wqkv + (size_t)gw * ND;
    float acc[NB];
#pragma unroll
    for (int b = 0; b < NB; b++) acc[b] = 0.f;
    for (int e = lane; e < ND; e += 32) {
        float wv = row[e];
#pragma unroll
        for (int b = 0; b < NB; b++) acc[b] += wv * ctx[b * ND + e];
    }
#pragma unroll
    for (int b = 0; b < NB; b++) {
#pragma unroll
        for (int off = 16; off; off >>= 1)
            acc[b] += __shfl_xor_sync(0xffffffffu, acc[b], off);
    }
    if (lane == 0) {
        float bias = bqkv[gw];
        float* dst;
        if (gw < ND)            dst = g_q0   + gw;
        else if (gw < 2 * ND)   dst = g_kcls + (gw - ND);
        else                    dst = g_vcls + (gw - 2 * ND);
#pragma unroll
        for (int b = 0; b < NB; b++) dst[b * ND] = acc[b] + bias;
    }
}

// ---------------- P2: u (128 blocks), t (128 blocks), ck (1 block) ----------
__global__ void __launch_bounds__(256) kP2(const float* __restrict__ Wqkv,
                                           const float* __restrict__ bqkv,
                                           const float* __restrict__ Wo,
                                           const float* __restrict__ bo) {
    int bx = blockIdx.x;
    if (bx < 128) {
        int h   = bx >> 3;
        int dsl = bx & 7;
        __shared__ float s_q[NB * HDm];
        for (int i = threadIdx.x; i < NB * HDm; i += blockDim.x) {
            int b = i >> 6, j = i & 63;
            s_q[i] = g_q0[b * ND + h * HDm + j];
        }
        __syncthreads();
        if (threadIdx.x < 128) {
            int d = dsl * 128 + threadIdx.x;
            float acc[NB];
#pragma unroll
            for (int b = 0; b < NB; b++) acc[b] = 0.f;
#pragma unroll 4
            for (int j = 0; j < HDm; j++) {
                float wv = __ldg(Wqkv + (size_t)(ND + h * HDm + j) * ND + d);
#pragma unroll
                for (int b = 0; b < NB; b++) acc[b] += s_q[b * HDm + j] * wv;
            }
#pragma unroll
            for (int b = 0; b < NB; b++)
                g_u[(size_t)(b * ND + d) * NHH + h] = acc[b];
        }
    } else if (bx < 256) {
        int d    = (bx - 128) * 8 + (threadIdx.x >> 5);
        int lane = threadIdx.x & 31;
        const float* row = Wo + (size_t)d * ND;
        float acc[NB];
#pragma unroll
        for (int b = 0; b < NB; b++) acc[b] = 0.f;
        for (int e = lane; e < ND; e += 32) {
            float wv = row[e];
#pragma unroll
            for (int b = 0; b < NB; b++) acc[b] += wv * g_vcls[b * ND + e];
        }
#pragma unroll
        for (int b = 0; b < NB; b++) {
#pragma unroll
            for (int off = 16; off; off >>= 1)
                acc[b] += __shfl_xor_sync(0xffffffffu, acc[b], off);
        }
        if (lane == 0) {
            float bias = bo[d];
#pragma unroll
            for (int b = 0; b < NB; b++) g_t[b * ND + d] = acc[b] + bias;
        }
    } else {
        int t = threadIdx.x;
        if (t < NB * NHH) {
            int b = t >> 4, h = t & 15;
            float ck = 0.f, s0 = 0.f;
            for (int j = 0; j < HDm; j++) {
                float q = g_q0[b * ND + h * HDm + j];
                ck += q * bqkv[ND + h * HDm + j];
                s0 += q * g_kcls[b * ND + h * HDm + j];
            }
            g_ck[t] = ck;
            g_scores[(size_t)t * NS] = s0 * 0.125f;
        }
    }
}

// ---------------- Pass A: scores + LayerNorm feature-map output ----------------
// block = (b, 64 tokens). 8 warps; warp w handles d = 8i+w; thread = 2 tokens
// (packed f32x2). Heads packed pairwise into 64-bit accumulators.
__global__ void __launch_bounds__(256) kA(const float* __restrict__ x,
                                          const float* __restrict__ gamma,
                                          const float* __restrict__ beta,
                                          float* __restrict__ out) {
    int b    = blockIdx.y;
    int p0   = blockIdx.x * 64;
    int tid  = threadIdx.x;
    int w    = tid >> 5;
    int lane = tid & 31;
    int p    = p0 + lane * 2;

    __shared__ float s_acc[8][64][18];   // [warp][token][head], padded to 18
    __shared__ float s_sum[8][64];
    __shared__ float s_sq[8][64];
    __shared__ float s_mu[64];
    __shared__ float s_rs[64];

    const float* xb = x   + (size_t)b * ND * HW;
    const float* tb = g_t + b * ND;
    const u64*   ub = (const u64*)(g_u + (size_t)b * ND * NHH);

    u64 acc0[8], acc1[8];   // [head-pair] for token0 / token1
#pragma unroll
    for (int i = 0; i < 8; i++) { acc0[i] = 0ull; acc1[i] = 0ull; }
    u64 lsum = 0ull, lsq = 0ull;

#pragma unroll 2
    for (int i = 0; i < 128; i++) {
        int d = i * 8 + w;
        size_t off = (size_t)d * HW + p;
        u64 xc2 = add2(ldg2(xb + off), ldg2(g_pe + off));
        float t = __ldg(tb + d);
        u64 r2 = add2(xc2, pack2(t, t));
        lsum = add2(lsum, r2);
        fma2(lsq, r2, r2);
        float xl, xh; unpack2(xc2, xl, xh);
        u64 xll = pack2(xl, xl), xhh = pack2(xh, xh);
        const ulonglong2* uu = (const ulonglong2*)(ub + (size_t)d * 8);
#pragma unroll
        for (int q = 0; q < 4; q++) {
            ulonglong2 u2 = __ldg(uu + q);
            fma2(acc0[2 * q],     u2.x, xll);
            fma2(acc0[2 * q + 1], u2.y, xll);
            fma2(acc1[2 * q],     u2.x, xhh);
            fma2(acc1[2 * q + 1], u2.y, xhh);
        }
    }

#pragma unroll
    for (int hp = 0; hp < 8; hp++) {
        *(u64*)&s_acc[w][lane * 2][hp * 2]     = acc0[hp];
        *(u64*)&s_acc[w][lane * 2 + 1][hp * 2] = acc1[hp];
    }
    {
        float a, c;
        unpack2(lsum, a, c); s_sum[w][lane * 2] = a; s_sum[w][lane * 2 + 1] = c;
        unpack2(lsq,  a, c); s_sq[w][lane * 2]  = a; s_sq[w][lane * 2 + 1]  = c;
    }
    __syncthreads();

    if (tid < 64) {
        float m = 0.f, q = 0.f;
#pragma unroll
        for (int ww = 0; ww < 8; ww++) { m += s_sum[ww][tid]; q += s_sq[ww][tid]; }
        float mu  = m * (1.f / 1024.f);
        float var = q * (1.f / 1024.f) - mu * mu;
        s_mu[tid] = mu;
        s_rs[tid] = rsqrtf(var + 1e-5f);
    }
    // scores: 1024 (h,tok) pairs
#pragma unroll
    for (int r = 0; r < 4; r++) {
        int idx = r * 256 + tid;
        int h = idx >> 6, tok = idx & 63;
        float sc = 0.f;
#pragma unroll
        for (int ww = 0; ww < 8; ww++) sc += s_acc[ww][tok][h];
        sc = (sc + __ldg(g_ck + b * NHH + h)) * 0.125f;
        g_scores[(size_t)(b * NHH + h) * NS + (p0 + tok + 1)] = sc;
    }
    __syncthreads();

    u64 rs2  = pack2(s_rs[lane * 2], s_rs[lane * 2 + 1]);
    u64 nmu2 = pack2(-s_mu[lane * 2], -s_mu[lane * 2 + 1]);
    float* ob = out + (size_t)b * ND * HW;
#pragma unroll 2
    for (int i = 0; i < 128; i++) {
        int d = i * 8 + w;
        size_t off = (size_t)d * HW + p;
        u64 xc2 = add2(ldg2(xb + off), ldg2(g_pe + off));
        float t = __ldg(tb + d);
        u64 r2 = add2(xc2, pack2(t, t));
        float gmv = __ldg(gamma + d), bv = __ldg(beta + d);
        u64 A2 = mul2(rs2, pack2(gmv, gmv));
        u64 B2 = fma2n(nmu2, A2, pack2(bv, bv));
        *(u64*)(ob + off) = fma2n(r2, A2, B2);
    }
}

// ---------------- Softmax over s (row = (b,h), len 4097) ----------------
__global__ void __launch_bounds__(256) kSM() {
    int bh = blockIdx.x;
    const float* sc = g_scores + (size_t)bh * NS;
    __shared__ float sred[8];
    __shared__ float sbc;
    int tid = threadIdx.x, w = tid >> 5, lane = tid & 31;

    float mx = -FLT_MAX;
    for (int s = tid; s < NS; s += 256) mx = fmaxf(mx, sc[s]);
#pragma unroll
    for (int off = 16; off; off >>= 1) mx = fmaxf(mx, __shfl_xor_sync(0xffffffffu, mx, off));
    if (lane == 0) sred[w] = mx;
    __syncthreads();
    if (tid == 0) {
        float m = sred[0];
#pragma unroll
        for (int ww = 1; ww < 8; ww++) m = fmaxf(m, sred[ww]);
        sbc = m;
    }
    __syncthreads();
    mx = sbc;
    __syncthreads();

    float sum = 0.f;
    for (int s = tid; s < NS; s += 256) sum += expf(sc[s] - mx);
#pragma unroll
    for (int off = 16; off; off >>= 1) sum += __shfl_xor_sync(0xffffffffu, sum, off);
    if (lane == 0) sred[w] = sum;
    __syncthreads();
    if (tid == 0) {
        float m = 0.f;
#pragma unroll
        for (int ww = 0; ww < 8; ww++) m += sred[ww];
        sbc = m;
    }
    __syncthreads();
    float inv = 1.f / sbc;

    int b = bh >> 4, h = bh & 15;
    for (int s = tid; s < NS; s += 256)
        g_probs[((size_t)b * NS + s) * NHH + h] = expf(sc[s] - mx) * inv;
}

// ---------------- Pass B: m[b][h][d] = sum_s probs * xc ----------------
// block = (b, 16 d's); warp w handles 2 d's; thread handles 4 s via float4
// loads; heads packed pairwise (f32x2).
#define SCH 512
__global__ void __launch_bounds__(256) kB(const float* __restrict__ x,
                                          const float* __restrict__ ctx) {
    int b     = blockIdx.x >> 6;
    int d0    = (blockIdx.x & 63) * 16;
    int tid   = threadIdx.x;
    int w     = tid >> 5, lane = tid & 31;
    int dbase = d0 + w * 2;

    __shared__ float2 s_pr[8][SCH + 4];   // [head-pair][s_local]

    u64 acc[8][2];                         // [head-pair][d]
#pragma unroll
    for (int hp = 0; hp < 8; hp++) { acc[hp][0] = 0ull; acc[hp][1] = 0ull; }

    const float* xb = x + (size_t)b * ND * HW;

    for (int c = 0; c < HW / SCH; c++) {
        const float4* src = (const float4*)(g_probs + ((size_t)b * NS + c * SCH + 1) * NHH);
#pragma unroll
        for (int k = 0; k < 8; k++) {
            int idx = k * 256 + tid;          // 0..2047
            int sl  = idx >> 2, q = idx & 3;
            float4 v = __ldg(src + idx);
            s_pr[q * 2][sl]     = make_float2(v.x, v.y);
            s_pr[q * 2 + 1][sl] = make_float2(v.z, v.w);
        }
        __syncthreads();

#pragma unroll
        for (int i = 0; i < 4; i++) {
            int sl = i * 128 + lane * 4;
            size_t pA = (size_t)dbase * HW + c * SCH + sl;
            size_t pB = pA + HW;
            ulonglong2 xa = __ldg((const ulonglong2*)(xb + pA));
            ulonglong2 pa = __ldg((const ulonglong2*)(g_pe + pA));
            ulonglong2 xbv = __ldg((const ulonglong2*)(xb + pB));
            ulonglong2 pb = __ldg((const ulonglong2*)(g_pe + pB));
            u64 xcA0 = add2(xa.x, pa.x);   // (s0,s1) for d0
            u64 xcA1 = add2(xa.y, pa.y);   // (s2,s3) for d0
            u64 xcB0 = add2(xbv.x, pb.x);
            u64 xcB1 = add2(xbv.y, pb.y);
            float a0, a1, a2, a3, b0, b1, b2, b3;
            unpack2(xcA0, a0, a1); unpack2(xcA1, a2, a3);
            unpack2(xcB0, b0, b1); unpack2(xcB1, b2, b3);
            u64 xd00 = pack2(a0, a0), xd01 = pack2(a1, a1);
            u64 xd02 = pack2(a2, a2), xd03 = pack2(a3, a3);
            u64 xd10 = pack2(b0, b0), xd11 = pack2(b1, b1);
            u64 xd12 = pack2(b2, b2), xd13 = pack2(b3, b3);
#pragma unroll
            for (int hp = 0; hp < 8; hp++) {
                ulonglong2 v01 = *(const ulonglong2*)&s_pr[hp][sl];
                ulonglong2 v23 = *(const ulonglong2*)&s_pr[hp][sl + 2];
                fma2(acc[hp][0], v01.x, xd00);
                fma2(acc[hp][0], v01.y, xd01);
                fma2(acc[hp][0], v23.x, xd02);
                fma2(acc[hp][0], v23.y, xd03);
                fma2(acc[hp][1], v01.x, xd10);
                fma2(acc[hp][1], v01.y, xd11);
                fma2(acc[hp][1], v23.x, xd12);
                fma2(acc[hp][1], v23.y, xd13);
            }
        }
        __syncthreads();
    }

    // cross-lane reduce (disjoint s-subsets per lane)
#pragma unroll
    for (int hp = 0; hp < 8; hp++)
#pragma unroll
        for (int dj = 0; dj < 2; dj++)
#pragma unroll
            for (int off = 16; off; off >>= 1) {
                u64 o = __shfl_xor_sync(0xffffffffu, acc[hp][dj], off);
                acc[hp][dj] = add2(acc[hp][dj], o);
            }

    if (lane == 0) {
#pragma unroll
        for (int hp = 0; hp < 8; hp++) {
            int h0 = 2 * hp, h1 = 2 * hp + 1;
            float p0a = g_probs[(size_t)b * NS * NHH + h0];
            float p0b = g_probs[(size_t)b * NS * NHH + h1];
#pragma unroll
            for (int dj = 0; dj < 2; dj++) {
                int d = dbase + dj;
                float m0, m1; unpack2(acc[hp][dj], m0, m1);
                float cv = ctx[b * ND + d];
                g_m[(size_t)(b * NHH + h0) * ND + d] = m0 + p0a * cv;
                g_m[(size_t)(b * NHH + h1) * ND + d] = m1 + p0b * cv;
            }
        }
    }
}

// ---------------- E1: cls_out = Wv . m + bv ----------
__global__ void __launch_bounds__(256) kE1(const float* __restrict__ Wqkv,
                                           const float* __restrict__ bqkv) {
    int dq   = blockIdx.x * 8 + (threadIdx.x >> 5);
    int lane = threadIdx.x & 31;
    int h    = dq >> 6;
    const float* row = Wqkv + (size_t)(2 * ND + dq) * ND;
    float acc[NB];
#pragma unroll
    for (int b = 0; b < NB; b++) acc[b] = 0.f;
    for (int e = lane; e < ND; e += 32) {
        float wv = row[e];
#pragma unroll
        for (int b = 0; b < NB; b++)
            acc[b] += wv * g_m[(size_t)(b * NHH + h) * ND + e];
    }
#pragma unroll
    for (int b = 0; b < NB; b++) {
#pragma unroll
        for (int off = 16; off; off >>= 1)
            acc[b] += __shfl_xor_sync(0xffffffffu, acc[b], off);
    }
    if (lane == 0) {
        float bias = bqkv[2 * ND + dq];
#pragma unroll
        for (int b = 0; b < NB; b++) g_clsout[b * ND + dq] = acc[b] + bias;
    }
}

// ---------------- E2a: resid = Wo.clsout + bo + ctx (warp per row, 128 blocks)
__global__ void __launch_bounds__(256) kE2a(const float* __restrict__ Wo,
                                            const float* __restrict__ bo,
                                            const float* __restrict__ ctx) {
    int d    = blockIdx.x * 8 + (threadIdx.x >> 5);
    int lane = threadIdx.x & 31;
    const float* row = Wo + (size_t)d * ND;
    float acc[NB];
#pragma unroll
    for (int b = 0; b < NB; b++) acc[b] = 0.f;
    for (int e = lane; e < ND; e += 32) {
        float wv = row[e];
#pragma unroll
        for (int b = 0; b < NB; b++) acc[b] += wv * g_clsout[b * ND + e];
    }
#pragma unroll
    for (int b = 0; b < NB; b++) {
#pragma unroll
        for (int off = 16; off; off >>= 1)
            acc[b] += __shfl_xor_sync(0xffffffffu, acc[b], off);
    }
    if (lane == 0) {
        float bias = bo[d];
#pragma unroll
        for (int b = 0; b < NB; b++)
            g_resid[b * ND + d] = acc[b] + bias + ctx[b * ND + d];
    }
}

// ---------------- E2b: LN over resid -> context out ----------
__global__ void __launch_bounds__(256) kE2b(const float* __restrict__ gamma,
                                            const float* __restrict__ beta,
                                            float* __restrict__ out_ctx) {
    int b   = blockIdx.x;
    int tid = threadIdx.x, w = tid >> 5, lane = tid & 31;
    __shared__ float red1[8], red2[8];
    __shared__ float s_mu, s_rs;
    const float* sr = g_resid + b * ND;

    float ls = 0.f, lq = 0.f;
    for (int d = tid; d < ND; d += 256) { float v = sr[d]; ls += v; lq += v * v; }
#pragma unroll
    for (int off = 16; off; off >>= 1) {
        ls += __shfl_xor_sync(0xffffffffu, ls, off);
        lq += __shfl_xor_sync(0xffffffffu, lq, off);
    }
    if (lane == 0) { red1[w] = ls; red2[w] = lq; }
    __syncthreads();
    if (tid == 0) {
        float m = 0.f, q = 0.f;
#pragma unroll
        for (int ww = 0; ww < 8; ww++) { m += red1[ww]; q += red2[ww]; }
        float mu  = m * (1.f / 1024.f);
        float var = q * (1.f / 1024.f) - mu * mu;
        s_mu = mu;
        s_rs = rsqrtf(var + 1e-5f);
    }
    __syncthreads();
    float mu = s_mu, rs = s_rs;
    for (int d = tid; d < ND; d += 256)
        out_ctx[b * ND + d] = (sr[d] - mu) * rs * gamma[d] + beta[d];
}

// ---------------- launch ----------------
extern "C" void kernel_launch(void* const* d_in, const int* in_sizes, int n_in,
                              void* d_out, int out_size) {
    const float* x     = (const float*)d_in[0];
    const float* ctx   = (const float*)d_in[1];
    const float* Wqkv  = (const float*)d_in[2];
    const float* bqkv  = (const float*)d_in[3];
    const float* Wo    = (const float*)d_in[4];
    const float* bo    = (const float*)d_in[5];
    const float* gamma = (const float*)d_in[6];
    const float* beta  = (const float*)d_in[7];
    float* out     = (float*)d_out;
    float* out_ctx = out + (size_t)NB * ND * HW;   // tuple: (feature_map, context)

    kP0<<<ND, 256>>>();
    kP1<<<384, 256>>>(Wqkv, bqkv, ctx);
    kP2<<<257, 256>>>(Wqkv, bqkv, Wo, bo);
    kA<<<dim3(HW / 64, NB), 256>>>(x, gamma, beta, out);
    kSM<<<NB * NHH, 256>>>();
    kB<<<NB * 64, 256>>>(x, ctx);
    kE1<<<128, 256>>>(Wqkv, bqkv);
    kE2a<<<128, 256>>>(Wo, bo, ctx);
    kE2b<<<NB, 256>>>(gamma, beta, out_ctx);
}

// round 7
// speedup vs baseline: 2.5540x; 1.8730x over previous
#include <cuda_runtime.h>
#include <math.h>
#include <float.h>

#define NB   8
#define ND   1024
#define NHH  16
#define HDm  64
#define HW   4096
#define NS   4097   // 1 CLS + 4096 tokens

typedef unsigned long long u64;

// ---------------- packed f32x2 helpers ----------------
__device__ __forceinline__ u64 pack2(float lo, float hi) {
    u64 r; asm("mov.b64 %0, {%1,%2};" : "=l"(r) : "f"(lo), "f"(hi)); return r;
}
__device__ __forceinline__ void unpack2(u64 v, float& lo, float& hi) {
    asm("mov.b64 {%0,%1}, %2;" : "=f"(lo), "=f"(hi) : "l"(v));
}
__device__ __forceinline__ void fma2(u64& d, u64 a, u64 b) {
    asm("fma.rn.f32x2 %0, %1, %2, %0;" : "+l"(d) : "l"(a), "l"(b));
}
__device__ __forceinline__ u64 fma2n(u64 a, u64 b, u64 c) {
    u64 d; asm("fma.rn.f32x2 %0, %1, %2, %3;" : "=l"(d) : "l"(a), "l"(b), "l"(c)); return d;
}
__device__ __forceinline__ u64 add2(u64 a, u64 b) {
    u64 d; asm("add.rn.f32x2 %0, %1, %2;" : "=l"(d) : "l"(a), "l"(b)); return d;
}
__device__ __forceinline__ u64 mul2(u64 a, u64 b) {
    u64 d; asm("mul.rn.f32x2 %0, %1, %2;" : "=l"(d) : "l"(a), "l"(b)); return d;
}
__device__ __forceinline__ u64 ldg2(const float* p) { return __ldg((const u64*)p); }

// ---------------- scratch (device globals; no allocations) ----------------
__device__ float g_pe[ND * HW];           // [d][p] positional encoding (16 MB)
__device__ float g_q0[NB * ND];
__device__ float g_kcls[NB * ND];
__device__ float g_vcls[NB * ND];
__device__ float g_u[NB * ND * NHH];      // [b][d][h]
__device__ u64   g_t2[NB * ND];           // t_b duplicated (t,t)
__device__ float g_ck[NB * NHH];
__device__ float g_scores[NB * NHH * NS];
__device__ float g_probsT[NB * NHH * HW]; // [b][h][token] (token = s-1)
__device__ float g_pcls[NB * NHH];        // prob of s=0 (CLS)
__device__ float g_nmu[NB * HW];          // -mu per token
__device__ float g_rs[NB * HW];           // rsqrt(var+eps) per token
__device__ float g_m[NB * NHH * ND];
__device__ float g_clsout[NB * ND];
__device__ float g_resid[NB * ND];

// ---------------- P0: positional encoding table ----------------
__global__ void kP0() {
    int d  = blockIdx.x;
    int e2 = d & ~1;
    float rate = (float)exp(-(double)e2 * (9.210340371976184 / 1024.0));
    bool iscos = (d & 1);
    int base = d * HW;
    for (int p = threadIdx.x; p < HW; p += blockDim.x) {
        float ang = (float)p * rate;
        g_pe[base + p] = iscos ? cosf(ang) : sinf(ang);
    }
}

// ---------------- P1: q0 / k_cls / v_cls ----------------
__global__ void __launch_bounds__(256) kP1(const float* __restrict__ Wqkv,
                                           const float* __restrict__ bqkv,
                                           const float* __restrict__ ctx) {
    int gw   = blockIdx.x * 8 + (threadIdx.x >> 5);
    int lane = threadIdx.x & 31;
    if (gw >= 3 * ND) return;
    const float* row = Wqkv + (size_t)gw * ND;
    float acc[NB];
#pragma unroll
    for (int b = 0; b < NB; b++) acc[b] = 0.f;
    for (int e = lane; e < ND; e += 32) {
        float wv = row[e];
#pragma unroll
        for (int b = 0; b < NB; b++) acc[b] += wv * ctx[b * ND + e];
    }
#pragma unroll
    for (int b = 0; b < NB; b++) {
#pragma unroll
        for (int off = 16; off; off >>= 1)
            acc[b] += __shfl_xor_sync(0xffffffffu, acc[b], off);
    }
    if (lane == 0) {
        float bias = bqkv[gw];
        float* dst;
        if (gw < ND)            dst = g_q0   + gw;
        else if (gw < 2 * ND)   dst = g_kcls + (gw - ND);
        else                    dst = g_vcls + (gw - 2 * ND);
#pragma unroll
        for (int b = 0; b < NB; b++) dst[b * ND] = acc[b] + bias;
    }
}

// ---------------- P2: u (128 blocks), t2 (128 blocks), ck (1 block) ---------
__global__ void __launch_bounds__(256) kP2(const float* __restrict__ Wqkv,
                                           const float* __restrict__ bqkv,
                                           const float* __restrict__ Wo,
                                           const float* __restrict__ bo) {
    int bx = blockIdx.x;
    if (bx < 128) {
        int h   = bx >> 3;
        int dsl = bx & 7;
        __shared__ float s_q[NB * HDm];
        for (int i = threadIdx.x; i < NB * HDm; i += blockDim.x) {
            int b = i >> 6, j = i & 63;
            s_q[i] = g_q0[b * ND + h * HDm + j];
        }
        __syncthreads();
        if (threadIdx.x < 128) {
            int d = dsl * 128 + threadIdx.x;
            float acc[NB];
#pragma unroll
            for (int b = 0; b < NB; b++) acc[b] = 0.f;
#pragma unroll 4
            for (int j = 0; j < HDm; j++) {
                float wv = __ldg(Wqkv + (size_t)(ND + h * HDm + j) * ND + d);
#pragma unroll
                for (int b = 0; b < NB; b++) acc[b] += s_q[b * HDm + j] * wv;
            }
#pragma unroll
            for (int b = 0; b < NB; b++)
                g_u[(size_t)(b * ND + d) * NHH + h] = acc[b];
        }
    } else if (bx < 256) {
        int d    = (bx - 128) * 8 + (threadIdx.x >> 5);
        int lane = threadIdx.x & 31;
        const float* row = Wo + (size_t)d * ND;
        float acc[NB];
#pragma unroll
        for (int b = 0; b < NB; b++) acc[b] = 0.f;
        for (int e = lane; e < ND; e += 32) {
            float wv = row[e];
#pragma unroll
            for (int b = 0; b < NB; b++) acc[b] += wv * g_vcls[b * ND + e];
        }
#pragma unroll
        for (int b = 0; b < NB; b++) {
#pragma unroll
            for (int off = 16; off; off >>= 1)
                acc[b] += __shfl_xor_sync(0xffffffffu, acc[b], off);
        }
        if (lane == 0) {
            float bias = bo[d];
#pragma unroll
            for (int b = 0; b < NB; b++) {
                float v = acc[b] + bias;
                g_t2[b * ND + d] = pack2(v, v);
            }
        }
    } else {
        int t = threadIdx.x;
        if (t < NB * NHH) {
            int b = t >> 4, h = t & 15;
            float ck = 0.f, s0 = 0.f;
            for (int j = 0; j < HDm; j++) {
                float q = g_q0[b * ND + h * HDm + j];
                ck += q * bqkv[ND + h * HDm + j];
                s0 += q * g_kcls[b * ND + h * HDm + j];
            }
            g_ck[t] = ck;
            g_scores[(size_t)t * NS] = s0 * 0.125f;
        }
    }
}

// ---------------- kA1: scores + LayerNorm statistics ----------------
// block = (b, 64 tokens). 8 warps; warp w handles d = 8i+w; thread = 2 tokens.
// Heads packed pairwise into 64-bit accumulators (token duplicated via movs).
__global__ void __launch_bounds__(256) kA1(const float* __restrict__ x) {
    int b    = blockIdx.y;
    int p0   = blockIdx.x * 64;
    int tid  = threadIdx.x;
    int w    = tid >> 5;
    int lane = tid & 31;
    int p    = p0 + lane * 2;

    __shared__ float s_acc[8][64][18];   // [warp][token][head], padded
    __shared__ float s_sum[8][64];
    __shared__ float s_sq[8][64];

    const float* xb = x   + (size_t)b * ND * HW;
    const u64*   tb = g_t2 + b * ND;
    const u64*   ub = (const u64*)(g_u + (size_t)b * ND * NHH);

    u64 acc0[8], acc1[8];   // [head-pair] for token0 / token1
#pragma unroll
    for (int i = 0; i < 8; i++) { acc0[i] = 0ull; acc1[i] = 0ull; }
    u64 lsum = 0ull, lsq = 0ull;

#pragma unroll 2
    for (int i = 0; i < 128; i++) {
        int d = i * 8 + w;
        size_t off = (size_t)d * HW + p;
        u64 xc2 = add2(ldg2(xb + off), ldg2(g_pe + off));
        u64 r2  = add2(xc2, __ldg(tb + d));
        lsum = add2(lsum, r2);
        fma2(lsq, r2, r2);
        float xl, xh; unpack2(xc2, xl, xh);
        u64 xll = pack2(xl, xl), xhh = pack2(xh, xh);
        const ulonglong2* uu = (const ulonglong2*)(ub + (size_t)d * 8);
#pragma unroll
        for (int q = 0; q < 4; q++) {
            ulonglong2 u2 = __ldg(uu + q);
            fma2(acc0[2 * q],     u2.x, xll);
            fma2(acc0[2 * q + 1], u2.y, xll);
            fma2(acc1[2 * q],     u2.x, xhh);
            fma2(acc1[2 * q + 1], u2.y, xhh);
        }
    }

#pragma unroll
    for (int hp = 0; hp < 8; hp++) {
        *(u64*)&s_acc[w][lane * 2][hp * 2]     = acc0[hp];
        *(u64*)&s_acc[w][lane * 2 + 1][hp * 2] = acc1[hp];
    }
    {
        float a, c;
        unpack2(lsum, a, c); s_sum[w][lane * 2] = a; s_sum[w][lane * 2 + 1] = c;
        unpack2(lsq,  a, c); s_sq[w][lane * 2]  = a; s_sq[w][lane * 2 + 1]  = c;
    }
    __syncthreads();

    if (tid < 64) {
        float m = 0.f, q = 0.f;
#pragma unroll
        for (int ww = 0; ww < 8; ww++) { m += s_sum[ww][tid]; q += s_sq[ww][tid]; }
        float mu  = m * (1.f / 1024.f);
        float var = q * (1.f / 1024.f) - mu * mu;
        g_nmu[b * HW + p0 + tid] = -mu;
        g_rs[b * HW + p0 + tid]  = rsqrtf(var + 1e-5f);
    }
    // scores: 1024 (h,tok) pairs
#pragma unroll
    for (int r = 0; r < 4; r++) {
        int idx = r * 256 + tid;
        int h = idx >> 6, tok = idx & 63;
        float sc = 0.f;
#pragma unroll
        for (int ww = 0; ww < 8; ww++) sc += s_acc[ww][tok][h];
        sc = (sc + __ldg(g_ck + b * NHH + h)) * 0.125f;
        g_scores[(size_t)(b * NHH + h) * NS + (p0 + tok + 1)] = sc;
    }
}

// ---------------- Softmax (row = (b,h), len 4097) -> probsT [b][h][token] ---
__global__ void __launch_bounds__(256) kSM() {
    int bh = blockIdx.x;
    const float* sc = g_scores + (size_t)bh * NS;
    __shared__ float sred[8];
    __shared__ float sbc;
    int tid = threadIdx.x, w = tid >> 5, lane = tid & 31;

    float mx = -FLT_MAX;
    for (int s = tid; s < NS; s += 256) mx = fmaxf(mx, sc[s]);
#pragma unroll
    for (int off = 16; off; off >>= 1) mx = fmaxf(mx, __shfl_xor_sync(0xffffffffu, mx, off));
    if (lane == 0) sred[w] = mx;
    __syncthreads();
    if (tid == 0) {
        float m = sred[0];
#pragma unroll
        for (int ww = 1; ww < 8; ww++) m = fmaxf(m, sred[ww]);
        sbc = m;
    }
    __syncthreads();
    mx = sbc;
    __syncthreads();

    float sum = 0.f;
    for (int s = tid; s < NS; s += 256) sum += expf(sc[s] - mx);
#pragma unroll
    for (int off = 16; off; off >>= 1) sum += __shfl_xor_sync(0xffffffffu, sum, off);
    if (lane == 0) sred[w] = sum;
    __syncthreads();
    if (tid == 0) {
        float m = 0.f;
#pragma unroll
        for (int ww = 0; ww < 8; ww++) m += sred[ww];
        sbc = m;
    }
    __syncthreads();
    float inv = 1.f / sbc;

    float* pT = g_probsT + (size_t)bh * HW;
    for (int s = tid; s < NS; s += 256) {
        float pv = expf(sc[s] - mx) * inv;
        if (s == 0) g_pcls[bh] = pv;
        else        pT[s - 1] = pv;
    }
}

// ---------------- kB: moment GEMM + fused LayerNorm feature-map write -------
// block = (b, 16 d); warp = 2 d; thread = 2 tokens/step; acc packed over the
// s-pair (natural layout of x loads and probsT LDS -> zero packing movs).
#define SCH 512
__global__ void __launch_bounds__(256) kB(const float* __restrict__ x,
                                          const float* __restrict__ ctx,
                                          const float* __restrict__ gamma,
                                          const float* __restrict__ beta,
                                          float* __restrict__ out) {
    int b   = blockIdx.x >> 6;
    int d0  = (blockIdx.x & 63) * 16;
    int tid = threadIdx.x;
    int w   = tid >> 5, lane = tid & 31;
    int dA  = d0 + w * 2;        // warp owns dA, dA+1

    __shared__ float s_pr[16][SCH + 8];

    u64 acc[16][2];
#pragma unroll
    for (int h = 0; h < 16; h++) { acc[h][0] = 0ull; acc[h][1] = 0ull; }

    const float* xb  = x + (size_t)b * ND * HW;
    const float* pT  = g_probsT + (size_t)b * NHH * HW;
    const float* nmu = g_nmu + b * HW;
    const float* rsv = g_rs  + b * HW;
    float* ob = out + (size_t)b * ND * HW;

    u64 t2A = __ldg(g_t2 + b * ND + dA);
    u64 t2B = __ldg(g_t2 + b * ND + dA + 1);
    float gA = __ldg(gamma + dA), gB = __ldg(gamma + dA + 1);
    float bA = __ldg(beta + dA),  bB = __ldg(beta + dA + 1);
    u64 gdA = pack2(gA, gA), gdB = pack2(gB, gB);
    u64 bdA = pack2(bA, bA), bdB = pack2(bB, bB);

    for (int c = 0; c < HW / SCH; c++) {
        // stage probsT chunk: straight copy, 16 rows x 512 floats
#pragma unroll
        for (int k = 0; k < 8; k++) {
            int idx = k * 256 + tid;          // 0..2047
            int h = idx >> 7, j = idx & 127;
            float4 v = __ldg((const float4*)(pT + (size_t)h * HW + c * SCH) + j);
            *(float4*)&s_pr[h][j * 4] = v;
        }
        __syncthreads();

#pragma unroll 2
        for (int i = 0; i < 8; i++) {
            int sl = i * 64 + lane * 2;
            int p  = c * SCH + sl;
            size_t offA = (size_t)dA * HW + p;
            u64 xcA = add2(ldg2(xb + offA), ldg2(g_pe + offA));
            u64 xcB = add2(ldg2(xb + offA + HW), ldg2(g_pe + offA + HW));

            // fused LayerNorm write for these 2 d x 2 tokens
            u64 nm2 = ldg2(nmu + p);
            u64 rs2 = ldg2(rsv + p);
            u64 AA = mul2(rs2, gdA);
            u64 AB = mul2(rs2, gdB);
            *(u64*)(ob + offA)      = fma2n(add2(add2(xcA, t2A), nm2), AA, bdA);
            *(u64*)(ob + offA + HW) = fma2n(add2(add2(xcB, t2B), nm2), AB, bdB);

#pragma unroll
            for (int h = 0; h < 16; h++) {
                u64 pr2 = *(const u64*)&s_pr[h][sl];
                fma2(acc[h][0], pr2, xcA);
                fma2(acc[h][1], pr2, xcB);
            }
        }
        __syncthreads();
    }

    // cross-lane reduce (disjoint s-subsets per lane)
#pragma unroll
    for (int h = 0; h < 16; h++)
#pragma unroll
        for (int dj = 0; dj < 2; dj++)
#pragma unroll
            for (int off = 16; off; off >>= 1) {
                u64 o = __shfl_xor_sync(0xffffffffu, acc[h][dj], off);
                acc[h][dj] = add2(acc[h][dj], o);
            }

    if (lane == 0) {
        float cv0 = ctx[b * ND + dA], cv1 = ctx[b * ND + dA + 1];
#pragma unroll
        for (int h = 0; h < 16; h++) {
            float pc = g_pcls[b * NHH + h];
            float lo, hi;
            unpack2(acc[h][0], lo, hi);
            g_m[(size_t)(b * NHH + h) * ND + dA]     = lo + hi + pc * cv0;
            unpack2(acc[h][1], lo, hi);
            g_m[(size_t)(b * NHH + h) * ND + dA + 1] = lo + hi + pc * cv1;
        }
    }
}

// ---------------- E1: cls_out = Wv . m + bv ----------
__global__ void __launch_bounds__(256) kE1(const float* __restrict__ Wqkv,
                                           const float* __restrict__ bqkv) {
    int dq   = blockIdx.x * 8 + (threadIdx.x >> 5);
    int lane = threadIdx.x & 31;
    int h    = dq >> 6;
    const float* row = Wqkv + (size_t)(2 * ND + dq) * ND;
    float acc[NB];
#pragma unroll
    for (int b = 0; b < NB; b++) acc[b] = 0.f;
    for (int e = lane; e < ND; e += 32) {
        float wv = row[e];
#pragma unroll
        for (int b = 0; b < NB; b++)
            acc[b] += wv * g_m[(size_t)(b * NHH + h) * ND + e];
    }
#pragma unroll
    for (int b = 0; b < NB; b++) {
#pragma unroll
        for (int off = 16; off; off >>= 1)
            acc[b] += __shfl_xor_sync(0xffffffffu, acc[b], off);
    }
    if (lane == 0) {
        float bias = bqkv[2 * ND + dq];
#pragma unroll
        for (int b = 0; b < NB; b++) g_clsout[b * ND + dq] = acc[b] + bias;
    }
}

// ---------------- E2a: resid = Wo.clsout + bo + ctx ----------
__global__ void __launch_bounds__(256) kE2a(const float* __restrict__ Wo,
                                            const float* __restrict__ bo,
                                            const float* __restrict__ ctx) {
    int d    = blockIdx.x * 8 + (threadIdx.x >> 5);
    int lane = threadIdx.x & 31;
    const float* row = Wo + (size_t)d * ND;
    float acc[NB];
#pragma unroll
    for (int b = 0; b < NB; b++) acc[b] = 0.f;
    for (int e = lane; e < ND; e += 32) {
        float wv = row[e];
#pragma unroll
        for (int b = 0; b < NB; b++) acc[b] += wv * g_clsout[b * ND + e];
    }
#pragma unroll
    for (int b = 0; b < NB; b++) {
#pragma unroll
        for (int off = 16; off; off >>= 1)
            acc[b] += __shfl_xor_sync(0xffffffffu, acc[b], off);
    }
    if (lane == 0) {
        float bias = bo[d];
#pragma unroll
        for (int b = 0; b < NB; b++)
            g_resid[b * ND + d] = acc[b] + bias + ctx[b * ND + d];
    }
}

// ---------------- E2b: LN over resid -> context out ----------
__global__ void __launch_bounds__(256) kE2b(const float* __restrict__ gamma,
                                            const float* __restrict__ beta,
                                            float* __restrict__ out_ctx) {
    int b   = blockIdx.x;
    int tid = threadIdx.x, w = tid >> 5, lane = tid & 31;
    __shared__ float red1[8], red2[8];
    __shared__ float s_mu, s_rs;
    const float* sr = g_resid + b * ND;

    float ls = 0.f, lq = 0.f;
    for (int d = tid; d < ND; d += 256) { float v = sr[d]; ls += v; lq += v * v; }
#pragma unroll
    for (int off = 16; off; off >>= 1) {
        ls += __shfl_xor_sync(0xffffffffu, ls, off);
        lq += __shfl_xor_sync(0xffffffffu, lq, off);
    }
    if (lane == 0) { red1[w] = ls; red2[w] = lq; }
    __syncthreads();
    if (tid == 0) {
        float m = 0.f, q = 0.f;
#pragma unroll
        for (int ww = 0; ww < 8; ww++) { m += red1[ww]; q += red2[ww]; }
        float mu  = m * (1.f / 1024.f);
        float var = q * (1.f / 1024.f) - mu * mu;
        s_mu = mu;
        s_rs = rsqrtf(var + 1e-5f);
    }
    __syncthreads();
    float mu = s_mu, rs = s_rs;
    for (int d = tid; d < ND; d += 256)
        out_ctx[b * ND + d] = (sr[d] - mu) * rs * gamma[d] + beta[d];
}

// ---------------- launch ----------------
extern "C" void kernel_launch(void* const* d_in, const int* in_sizes, int n_in,
                              void* d_out, int out_size) {
    const float* x     = (const float*)d_in[0];
    const float* ctx   = (const float*)d_in[1];
    const float* Wqkv  = (const float*)d_in[2];
    const float* bqkv  = (const float*)d_in[3];
    const float* Wo    = (const float*)d_in[4];
    const float* bo    = (const float*)d_in[5];
    const float* gamma = (const float*)d_in[6];
    const float* beta  = (const float*)d_in[7];
    float* out     = (float*)d_out;
    float* out_ctx = out + (size_t)NB * ND * HW;   // tuple: (feature_map, context)

    kP0<<<ND, 256>>>();
    kP1<<<384, 256>>>(Wqkv, bqkv, ctx);
    kP2<<<257, 256>>>(Wqkv, bqkv, Wo, bo);
    kA1<<<dim3(HW / 64, NB), 256>>>(x);
    kSM<<<NB * NHH, 256>>>();
    kB<<<NB * 64, 256>>>(x, ctx, gamma, beta, out);
    kE1<<<128, 256>>>(Wqkv, bqkv);
    kE2a<<<128, 256>>>(Wo, bo, ctx);
    kE2b<<<NB, 256>>>(gamma, beta, out_ctx);
}